// round 3
// baseline (speedup 1.0000x reference)
#include <cuda_runtime.h>

#define D_IN 8
#define HID 64
#define EPS 1e-5f

typedef unsigned long long u64;

__device__ __forceinline__ u64 pack2(float lo, float hi) {
    u64 r; asm("mov.b64 %0,{%1,%2};" : "=l"(r) : "f"(lo), "f"(hi)); return r;
}
__device__ __forceinline__ void unpack2(u64 v, float& lo, float& hi) {
    asm("mov.b64 {%0,%1},%2;" : "=f"(lo), "=f"(hi) : "l"(v));
}
__device__ __forceinline__ u64 ffma2(u64 a, u64 b, u64 c) {
    u64 d; asm("fma.rn.f32x2 %0,%1,%2,%3;" : "=l"(d) : "l"(a), "l"(b), "l"(c)); return d;
}
__device__ __forceinline__ float tanh_fast(float x) {
    float y; asm("tanh.approx.f32 %0,%1;" : "=f"(y) : "f"(x)); return y;
}

// LayerNorm + tanh: input = 32 packed k-pairs (acc), output = 64 scalars h.
__device__ __forceinline__ void ln_tanh_packed(const u64* __restrict__ acc,
                                               float* __restrict__ h,
                                               const float* __restrict__ g,
                                               const float* __restrict__ be) {
    float s = 0.f;
#pragma unroll
    for (int kp = 0; kp < 32; kp++) {
        unpack2(acc[kp], h[2 * kp], h[2 * kp + 1]);
        s += h[2 * kp] + h[2 * kp + 1];
    }
    float m = s * (1.0f / HID);
    float ss = 0.f;
#pragma unroll
    for (int i = 0; i < HID; i++) { float d = h[i] - m; ss = fmaf(d, d, ss); }
    float inv = rsqrtf(ss * (1.0f / HID) + EPS);
#pragma unroll
    for (int i = 0; i < HID; i++) {
        h[i] = tanh_fast(fmaf((h[i] - m) * inv, g[i], be[i]));
    }
}

__global__ __launch_bounds__(128) void edge_mlp_kernel(
    const float* __restrict__ x,
    const int* __restrict__ ei,
    const float* __restrict__ W0, const float* __restrict__ b0,
    const float* __restrict__ g0, const float* __restrict__ be0,
    const float* __restrict__ W1, const float* __restrict__ b1,
    const float* __restrict__ g1, const float* __restrict__ be1,
    const float* __restrict__ W2, const float* __restrict__ b2,
    const float* __restrict__ g2, const float* __restrict__ be2,
    const float* __restrict__ W3, const float* __restrict__ b3,
    float* __restrict__ out, int n_edges)
{
    __shared__ __align__(16) float sW0[2 * D_IN * HID];   // 16x64
    __shared__ __align__(16) float sW1[HID * HID];        // 64x64
    __shared__ __align__(16) float sW2[HID * HID];        // 64x64
    __shared__ __align__(16) float sW3[HID];
    __shared__ __align__(16) float sb0[HID], sb1[HID], sb2[HID];
    __shared__ __align__(16) float sg0[HID], sbe0[HID];
    __shared__ __align__(16) float sg1[HID], sbe1[HID];
    __shared__ __align__(16) float sg2[HID], sbe2[HID];
    __shared__ float sb3;

    const int t = threadIdx.x;
    for (int i = t; i < 2 * D_IN * HID; i += blockDim.x) sW0[i] = W0[i];
    for (int i = t; i < HID * HID; i += blockDim.x) sW1[i] = W1[i];
    for (int i = t; i < HID * HID; i += blockDim.x) sW2[i] = W2[i];
    if (t < HID) {
        sW3[t] = W3[t];
        sb0[t] = b0[t]; sb1[t] = b1[t]; sb2[t] = b2[t];
        sg0[t] = g0[t]; sbe0[t] = be0[t];
        sg1[t] = g1[t]; sbe1[t] = be1[t];
        sg2[t] = g2[t]; sbe2[t] = be2[t];
    }
    if (t == 0) sb3 = b3[0];
    __syncthreads();

    const float4* __restrict__ x4 = (const float4*)x;
    const int stride = gridDim.x * blockDim.x;

    for (int e = blockIdx.x * blockDim.x + threadIdx.x; e < n_edges; e += stride) {
        const int s = ei[e];
        const int d = ei[n_edges + e];
        float in[2 * D_IN];
        {
            float4 a0 = x4[2 * s], a1 = x4[2 * s + 1];
            float4 c0 = x4[2 * d], c1 = x4[2 * d + 1];
            in[0] = a0.x; in[1] = a0.y; in[2] = a0.z; in[3] = a0.w;
            in[4] = a1.x; in[5] = a1.y; in[6] = a1.z; in[7] = a1.w;
            in[8] = c0.x; in[9] = c0.y; in[10] = c0.z; in[11] = c0.w;
            in[12] = c1.x; in[13] = c1.y; in[14] = c1.z; in[15] = c1.w;
        }

        u64 acc[32];
        float h[HID];

        // ---- Layer 0: [16] @ W0[16x64] + b0 (packed k-pairs) ----
#pragma unroll
        for (int kp = 0; kp < 32; kp++) acc[kp] = *(const u64*)&sb0[2 * kp];
#pragma unroll
        for (int j = 0; j < 2 * D_IN; j++) {
            u64 hs = pack2(in[j], in[j]);
            const ulonglong2* wrow = (const ulonglong2*)&sW0[j * HID];
#pragma unroll
            for (int q = 0; q < 16; q++) {
                ulonglong2 w = wrow[q];
                acc[2 * q]     = ffma2(hs, w.x, acc[2 * q]);
                acc[2 * q + 1] = ffma2(hs, w.y, acc[2 * q + 1]);
            }
        }
        ln_tanh_packed(acc, h, sg0, sbe0);

        // ---- Layer 1: [64] @ W1[64x64] + b1 ----
#pragma unroll
        for (int kp = 0; kp < 32; kp++) acc[kp] = *(const u64*)&sb1[2 * kp];
#pragma unroll 4
        for (int j = 0; j < HID; j++) {
            u64 hs = pack2(h[j], h[j]);
            const ulonglong2* wrow = (const ulonglong2*)&sW1[j * HID];
#pragma unroll
            for (int q = 0; q < 16; q++) {
                ulonglong2 w = wrow[q];
                acc[2 * q]     = ffma2(hs, w.x, acc[2 * q]);
                acc[2 * q + 1] = ffma2(hs, w.y, acc[2 * q + 1]);
            }
        }
        ln_tanh_packed(acc, h, sg1, sbe1);

        // ---- Layer 2: [64] @ W2[64x64] + b2 ----
#pragma unroll
        for (int kp = 0; kp < 32; kp++) acc[kp] = *(const u64*)&sb2[2 * kp];
#pragma unroll 4
        for (int j = 0; j < HID; j++) {
            u64 hs = pack2(h[j], h[j]);
            const ulonglong2* wrow = (const ulonglong2*)&sW2[j * HID];
#pragma unroll
            for (int q = 0; q < 16; q++) {
                ulonglong2 w = wrow[q];
                acc[2 * q]     = ffma2(hs, w.x, acc[2 * q]);
                acc[2 * q + 1] = ffma2(hs, w.y, acc[2 * q + 1]);
            }
        }
        ln_tanh_packed(acc, h, sg2, sbe2);

        // ---- Layer 3: [64] @ W3[64x1] + b3 ----
        float o = sb3;
#pragma unroll
        for (int j = 0; j < HID; j++) o = fmaf(h[j], sW3[j], o);

        out[e] = o;
    }
}

extern "C" void kernel_launch(void* const* d_in, const int* in_sizes, int n_in,
                              void* d_out, int out_size) {
    const float* x   = (const float*)d_in[0];
    const int*   ei  = (const int*)d_in[1];
    const float* W0 = (const float*)d_in[2];
    const float* b0 = (const float*)d_in[3];
    const float* g0 = (const float*)d_in[4];
    const float* be0 = (const float*)d_in[5];
    const float* W1 = (const float*)d_in[6];
    const float* b1 = (const float*)d_in[7];
    const float* g1 = (const float*)d_in[8];
    const float* be1 = (const float*)d_in[9];
    const float* W2 = (const float*)d_in[10];
    const float* b2 = (const float*)d_in[11];
    const float* g2 = (const float*)d_in[12];
    const float* be2 = (const float*)d_in[13];
    const float* W3 = (const float*)d_in[14];
    const float* b3 = (const float*)d_in[15];
    float* out = (float*)d_out;

    const int n_edges = in_sizes[1] / 2;

    const int threads = 128;
    const int blocks = 148 * 16;
    edge_mlp_kernel<<<blocks, threads>>>(x, ei,
                                         W0, b0, g0, be0,
                                         W1, b1, g1, be1,
                                         W2, b2, g2, be2,
                                         W3, b3, out, n_edges);
}

// round 4
// speedup vs baseline: 1.0355x; 1.0355x over previous
#include <cuda_runtime.h>

#define D_IN 8
#define HID 64
#define EPS 1e-5f

typedef unsigned long long u64;

__device__ __forceinline__ u64 pack2(float lo, float hi) {
    u64 r; asm("mov.b64 %0,{%1,%2};" : "=l"(r) : "f"(lo), "f"(hi)); return r;
}
__device__ __forceinline__ void unpack2(u64 v, float& lo, float& hi) {
    asm("mov.b64 {%0,%1},%2;" : "=f"(lo), "=f"(hi) : "l"(v));
}
__device__ __forceinline__ u64 ffma2(u64 a, u64 b, u64 c) {
    u64 d; asm("fma.rn.f32x2 %0,%1,%2,%3;" : "=l"(d) : "l"(a), "l"(b), "l"(c)); return d;
}
__device__ __forceinline__ float tanh_fast(float x) {
    float y; asm("tanh.approx.f32 %0,%1;" : "=f"(y) : "f"(x)); return y;
}

// LayerNorm + tanh: input = 32 packed k-pairs (acc), output = 64 scalars h.
__device__ __forceinline__ void ln_tanh_packed(const u64* __restrict__ acc,
                                               float* __restrict__ h,
                                               const float* __restrict__ g,
                                               const float* __restrict__ be) {
    float s = 0.f;
#pragma unroll
    for (int kp = 0; kp < 32; kp++) {
        unpack2(acc[kp], h[2 * kp], h[2 * kp + 1]);
        s += h[2 * kp] + h[2 * kp + 1];
    }
    float m = s * (1.0f / HID);
    float ss = 0.f;
#pragma unroll
    for (int i = 0; i < HID; i++) { float d = h[i] - m; ss = fmaf(d, d, ss); }
    float inv = rsqrtf(ss * (1.0f / HID) + EPS);
#pragma unroll
    for (int i = 0; i < HID; i++) {
        h[i] = tanh_fast(fmaf((h[i] - m) * inv, g[i], be[i]));
    }
}

__global__ __launch_bounds__(128, 1) void edge_mlp_kernel(
    const float* __restrict__ x,
    const int* __restrict__ ei,
    const float* __restrict__ W0, const float* __restrict__ b0,
    const float* __restrict__ g0, const float* __restrict__ be0,
    const float* __restrict__ W1, const float* __restrict__ b1,
    const float* __restrict__ g1, const float* __restrict__ be1,
    const float* __restrict__ W2, const float* __restrict__ b2,
    const float* __restrict__ g2, const float* __restrict__ be2,
    const float* __restrict__ W3, const float* __restrict__ b3,
    float* __restrict__ out, int n_edges)
{
    __shared__ __align__(16) float sW0[2 * D_IN * HID];   // 16x64
    __shared__ __align__(16) float sW1[HID * HID];        // 64x64
    __shared__ __align__(16) float sW2[HID * HID];        // 64x64
    __shared__ __align__(16) float sW3[HID];
    __shared__ __align__(16) float sb0[HID], sb1[HID], sb2[HID];
    __shared__ __align__(16) float sg0[HID], sbe0[HID];
    __shared__ __align__(16) float sg1[HID], sbe1[HID];
    __shared__ __align__(16) float sg2[HID], sbe2[HID];
    __shared__ float sb3;

    const int t = threadIdx.x;
    for (int i = t; i < 2 * D_IN * HID; i += blockDim.x) sW0[i] = W0[i];
    for (int i = t; i < HID * HID; i += blockDim.x) sW1[i] = W1[i];
    for (int i = t; i < HID * HID; i += blockDim.x) sW2[i] = W2[i];
    if (t < HID) {
        sW3[t] = W3[t];
        sb0[t] = b0[t]; sb1[t] = b1[t]; sb2[t] = b2[t];
        sg0[t] = g0[t]; sbe0[t] = be0[t];
        sg1[t] = g1[t]; sbe1[t] = be1[t];
        sg2[t] = g2[t]; sbe2[t] = be2[t];
    }
    if (t == 0) sb3 = b3[0];
    __syncthreads();

    const float4* __restrict__ x4 = (const float4*)x;
    const int stride = gridDim.x * blockDim.x;

    for (int e = blockIdx.x * blockDim.x + threadIdx.x; e < n_edges; e += stride) {
        const int s = ei[e];
        const int d = ei[n_edges + e];
        float in[2 * D_IN];
        {
            float4 a0 = x4[2 * s], a1 = x4[2 * s + 1];
            float4 c0 = x4[2 * d], c1 = x4[2 * d + 1];
            in[0] = a0.x; in[1] = a0.y; in[2] = a0.z; in[3] = a0.w;
            in[4] = a1.x; in[5] = a1.y; in[6] = a1.z; in[7] = a1.w;
            in[8] = c0.x; in[9] = c0.y; in[10] = c0.z; in[11] = c0.w;
            in[12] = c1.x; in[13] = c1.y; in[14] = c1.z; in[15] = c1.w;
        }

        u64 acc[32];
        float h[HID];

        // ---- Layer 0: [16] @ W0[16x64] + b0 (packed k-pairs) ----
#pragma unroll
        for (int kp = 0; kp < 32; kp++) acc[kp] = *(const u64*)&sb0[2 * kp];
#pragma unroll
        for (int j = 0; j < 2 * D_IN; j++) {
            u64 hs = pack2(in[j], in[j]);
            const ulonglong2* wrow = (const ulonglong2*)&sW0[j * HID];
#pragma unroll
            for (int q = 0; q < 16; q++) {
                ulonglong2 w = wrow[q];
                acc[2 * q]     = ffma2(hs, w.x, acc[2 * q]);
                acc[2 * q + 1] = ffma2(hs, w.y, acc[2 * q + 1]);
            }
        }
        ln_tanh_packed(acc, h, sg0, sbe0);

        // ---- Layer 1: [64] @ W1[64x64] + b1 ----
#pragma unroll
        for (int kp = 0; kp < 32; kp++) acc[kp] = *(const u64*)&sb1[2 * kp];
#pragma unroll 4
        for (int j = 0; j < HID; j++) {
            u64 hs = pack2(h[j], h[j]);
            const ulonglong2* wrow = (const ulonglong2*)&sW1[j * HID];
#pragma unroll
            for (int q = 0; q < 16; q++) {
                ulonglong2 w = wrow[q];
                acc[2 * q]     = ffma2(hs, w.x, acc[2 * q]);
                acc[2 * q + 1] = ffma2(hs, w.y, acc[2 * q + 1]);
            }
        }
        ln_tanh_packed(acc, h, sg1, sbe1);

        // ---- Layer 2: [64] @ W2[64x64] + b2 ----
#pragma unroll
        for (int kp = 0; kp < 32; kp++) acc[kp] = *(const u64*)&sb2[2 * kp];
#pragma unroll 4
        for (int j = 0; j < HID; j++) {
            u64 hs = pack2(h[j], h[j]);
            const ulonglong2* wrow = (const ulonglong2*)&sW2[j * HID];
#pragma unroll
            for (int q = 0; q < 16; q++) {
                ulonglong2 w = wrow[q];
                acc[2 * q]     = ffma2(hs, w.x, acc[2 * q]);
                acc[2 * q + 1] = ffma2(hs, w.y, acc[2 * q + 1]);
            }
        }
        ln_tanh_packed(acc, h, sg2, sbe2);

        // ---- Layer 3: [64] @ W3[64x1] + b3 ----
        float o = sb3;
#pragma unroll
        for (int j = 0; j < HID; j++) o = fmaf(h[j], sW3[j], o);

        out[e] = o;
    }
}

extern "C" void kernel_launch(void* const* d_in, const int* in_sizes, int n_in,
                              void* d_out, int out_size) {
    const float* x   = (const float*)d_in[0];
    const int*   ei  = (const int*)d_in[1];
    const float* W0 = (const float*)d_in[2];
    const float* b0 = (const float*)d_in[3];
    const float* g0 = (const float*)d_in[4];
    const float* be0 = (const float*)d_in[5];
    const float* W1 = (const float*)d_in[6];
    const float* b1 = (const float*)d_in[7];
    const float* g1 = (const float*)d_in[8];
    const float* be1 = (const float*)d_in[9];
    const float* W2 = (const float*)d_in[10];
    const float* b2 = (const float*)d_in[11];
    const float* g2 = (const float*)d_in[12];
    const float* be2 = (const float*)d_in[13];
    const float* W3 = (const float*)d_in[14];
    const float* b3 = (const float*)d_in[15];
    float* out = (float*)d_out;

    const int n_edges = in_sizes[1] / 2;

    const int threads = 128;
    const int blocks = 148 * 4;   // grid-stride; balanced across residency 1-4
    edge_mlp_kernel<<<blocks, threads>>>(x, ei,
                                         W0, b0, g0, be0,
                                         W1, b1, g1, be1,
                                         W2, b2, g2, be2,
                                         W3, b3, out, n_edges);
}